// round 5
// baseline (speedup 1.0000x reference)
#include <cuda_runtime.h>

// Fused 6-layer ReLU RNN + FC + log_softmax, diagonal-wavefront persistent kernel.
// T=1024, B=2048, IN=2, H=20, L=6, C=2.
// Packing: 2 batch elements per thread as f32x2 (fma.rn.f32x2 / FFMA2).
// CTA = 8 batch-pairs x 20 neuron-threads = 160 threads, grid = 128 CTAs.
// R2: forced 16B alignment on shared arrays read via 128-bit LDS (trap fix).

#define TT 1024
#define BB 2048
#define HH 20
#define LL 6
#define PP 8          // batch-pairs per CTA
#define PSTR 22       // padded h-row stride in 8B units (conflict-free, 16B-aligned)
#define NTH 160
#define NCTA 128

typedef unsigned long long u64;

__device__ __forceinline__ u64 f2fma(u64 a, u64 b, u64 c) {
    u64 r; asm("fma.rn.f32x2 %0, %1, %2, %3;" : "=l"(r) : "l"(a), "l"(b), "l"(c)); return r;
}
__device__ __forceinline__ u64 f2add(u64 a, u64 b) {
    u64 r; asm("add.rn.f32x2 %0, %1, %2;" : "=l"(r) : "l"(a), "l"(b)); return r;
}
__device__ __forceinline__ u64 dup2(float x) {
    u64 r; asm("mov.b64 %0, {%1, %1};" : "=l"(r) : "f"(x)); return r;
}
__device__ __forceinline__ u64 pk2(float lo, float hi) {
    u64 r; asm("mov.b64 %0, {%1, %2};" : "=l"(r) : "f"(lo), "f"(hi)); return r;
}
__device__ __forceinline__ void unpk(u64 a, float& lo, float& hi) {
    asm("mov.b64 {%0, %1}, %2;" : "=f"(lo), "=f"(hi) : "l"(a));
}

__global__ __launch_bounds__(NTH, 1) void rnn_wavefront_kernel(
    const float* __restrict__ x,     // [T, B, 2]
    const float* __restrict__ Wih0,  // [H, 2]
    const float* __restrict__ Wih,   // [L-1, H, H]
    const float* __restrict__ Whh,   // [L, H, H]
    const float* __restrict__ bih,   // [L, H]
    const float* __restrict__ bhh,   // [L, H]
    const float* __restrict__ fcw,   // [2, H]
    const float* __restrict__ fcb,   // [2]
    float* __restrict__ out)         // [T, B, 2]
{
    // --- shared memory (all 128-bit-loaded arrays forced to 16B alignment) ---
    __shared__ __align__(16) u64  hb[2][LL][PP * PSTR];   // double-buffered h state, f32x2 per pair
    __shared__ __align__(16) u64  whh2[LL][HH][HH];       // Whh, each element duplicated (w,w)
    __shared__ __align__(16) float wihs[LL - 1][HH][HH];  // Wih (layers 1..5), plain f32
    __shared__ __align__(16) u64  wih0d[HH][2];           // layer-0 input weights, duplicated
    __shared__ __align__(16) u64  fcw2[2][HH];            // fc weights, duplicated
    __shared__ __align__(16) u64  logitb[2][PP][2];       // double-buffered logits per pair

    const int tid = threadIdx.x;

    // --- stage weights into smem ---
    for (int i = tid; i < LL * HH * HH; i += NTH)       ((u64*)whh2)[i]  = dup2(Whh[i]);
    for (int i = tid; i < (LL - 1) * HH * HH; i += NTH) ((float*)wihs)[i] = Wih[i];
    for (int i = tid; i < HH * 2; i += NTH)             ((u64*)wih0d)[i] = dup2(Wih0[i]);
    for (int i = tid; i < 2 * HH; i += NTH)             ((u64*)fcw2)[i]  = dup2(fcw[i]);
    for (int i = tid; i < 2 * LL * PP * PSTR; i += NTH) ((u64*)hb)[i]    = 0ull;
    for (int i = tid; i < 2 * PP * 2; i += NTH)         ((u64*)logitb)[i] = 0ull;

    const int p = tid & 7;        // pair within CTA
    const int j = tid >> 3;       // neuron 0..19
    const int pg = blockIdx.x * PP + p;   // global pair 0..1023
    const int b0 = pg, b1 = pg + (BB / 2);

    // per-thread biases (b_ih + b_hh), duplicated
    u64 bj[LL];
#pragma unroll
    for (int l = 0; l < LL; l++) bj[l] = dup2(bih[l * HH + j] + bhh[l * HH + j]);
    const float fcb0 = fcb[0], fcb1 = fcb[1];

    __syncthreads();

    const float2* __restrict__ x2 = (const float2*)x;   // x2[t*BB + b]
    float2 xa = x2[b0];
    float2 xb = x2[b1];

    for (int tau = 0; tau < TT + 7; ++tau) {
        const int A = tau & 1;
        const u64(&rb)[LL][PP * PSTR] = hb[A];       // read buffer (last tick)
        u64(&wb)[LL][PP * PSTR] = hb[A ^ 1];         // write buffer (this tick)

        // ---- layers 1..5 : h_l(t) = relu( Wih_l h_{l-1}(t) + Whh_l h_l(t-1) + b ), t = tau - l
#pragma unroll
        for (int l = 1; l < LL; l++) {
            if ((unsigned)(tau - l) < TT) {
                const ulonglong2* hs = (const ulonglong2*)&rb[l][p * PSTR];
                const ulonglong2* hi = (const ulonglong2*)&rb[l - 1][p * PSTR];
                const ulonglong2* wh = (const ulonglong2*)&whh2[l][j][0];
                const float4* wi = (const float4*)&wihs[l - 1][j][0];
                u64 a0 = bj[l], a1 = 0ull, a2 = 0ull, a3 = 0ull;
#pragma unroll
                for (int q = 0; q < 5; q++) {
                    ulonglong2 w0 = wh[q], h0 = hs[q];
                    ulonglong2 w1 = wh[q + 5], h1 = hs[q + 5];
                    a0 = f2fma(w0.x, h0.x, a0); a0 = f2fma(w0.y, h0.y, a0);
                    a1 = f2fma(w1.x, h1.x, a1); a1 = f2fma(w1.y, h1.y, a1);
                    float4 f = wi[q];
                    ulonglong2 i0 = hi[2 * q], i1 = hi[2 * q + 1];
                    a2 = f2fma(dup2(f.x), i0.x, a2); a2 = f2fma(dup2(f.y), i0.y, a2);
                    a3 = f2fma(dup2(f.z), i1.x, a3); a3 = f2fma(dup2(f.w), i1.y, a3);
                }
                u64 s = f2add(f2add(a0, a1), f2add(a2, a3));
                float lo, hi2; unpk(s, lo, hi2);
                lo = fmaxf(lo, 0.0f); hi2 = fmaxf(hi2, 0.0f);
                *(float2*)&wb[l][p * PSTR + j] = make_float2(lo, hi2);
            }
        }

        // ---- layer 0 : input dim 2, t = tau
        if (tau < TT) {
            const ulonglong2* hs = (const ulonglong2*)&rb[0][p * PSTR];
            const ulonglong2* wh = (const ulonglong2*)&whh2[0][j][0];
            u64 a0 = bj[0], a1 = 0ull, a2 = 0ull;
            a1 = f2fma(wih0d[j][0], pk2(xa.x, xb.x), a1);
            a2 = f2fma(wih0d[j][1], pk2(xa.y, xb.y), a2);
#pragma unroll
            for (int q = 0; q < 5; q++) {
                ulonglong2 w0 = wh[q], h0 = hs[q];
                ulonglong2 w1 = wh[q + 5], h1 = hs[q + 5];
                a0 = f2fma(w0.x, h0.x, a0); a0 = f2fma(w0.y, h0.y, a0);
                a1 = f2fma(w1.x, h1.x, a1); a1 = f2fma(w1.y, h1.y, a1);
            }
            u64 s = f2add(f2add(a0, a1), a2);
            float lo, hi2; unpk(s, lo, hi2);
            lo = fmaxf(lo, 0.0f); hi2 = fmaxf(hi2, 0.0f);
            *(float2*)&wb[0][p * PSTR + j] = make_float2(lo, hi2);

            // prefetch next x
            const int tn = tau + 1;
            if (tn < TT) {
                xa = x2[tn * BB + b0];
                xb = x2[tn * BB + b1];
            }
        }

        // ---- fc stage (j==0 -> class 0, j==4 -> class 1), t = tau - 6
        if ((j == 0 || j == 4) && (unsigned)(tau - 6) < TT) {
            const int c = j >> 2;
            const ulonglong2* h5 = (const ulonglong2*)&rb[5][p * PSTR];
            const ulonglong2* fw = (const ulonglong2*)&fcw2[c][0];
            u64 a0 = dup2(c ? fcb1 : fcb0), a1 = 0ull;
#pragma unroll
            for (int q = 0; q < 5; q++) {
                ulonglong2 w0 = fw[q], h0 = h5[q];
                ulonglong2 w1 = fw[q + 5], h1 = h5[q + 5];
                a0 = f2fma(w0.x, h0.x, a0); a0 = f2fma(w0.y, h0.y, a0);
                a1 = f2fma(w1.x, h1.x, a1); a1 = f2fma(w1.y, h1.y, a1);
            }
            logitb[A ^ 1][p][c] = f2add(a0, a1);
        }

        // ---- log_softmax + store (j==8 -> batch b0, j==12 -> batch b1), t = tau - 7
        if ((j == 8 || j == 12) && (unsigned)(tau - 7) < TT) {
            const int t = tau - 7;
            const int which = (j >> 2) - 2;          // 0 or 1
            ulonglong2 lg = *(const ulonglong2*)&logitb[A][p][0];
            float c0a, c0b, c1a, c1b;
            unpk(lg.x, c0a, c0b);   // class-0 logits: (batch b0, batch b1)
            unpk(lg.y, c1a, c1b);   // class-1 logits
            float u0 = which ? c0b : c0a;
            float u1 = which ? c1b : c1a;
            float m = fmaxf(u0, u1);
            float lse = m + __logf(1.0f + __expf(fminf(u0, u1) - m));
            const int b = which ? b1 : b0;
            *(float2*)&out[(size_t)(t * BB + b) * 2] = make_float2(u0 - lse, u1 - lse);
        }

        __syncthreads();
    }
}

extern "C" void kernel_launch(void* const* d_in, const int* in_sizes, int n_in,
                              void* d_out, int out_size) {
    const float* x    = (const float*)d_in[0];
    const float* Wih0 = (const float*)d_in[1];
    const float* Wih  = (const float*)d_in[2];
    const float* Whh  = (const float*)d_in[3];
    const float* bih  = (const float*)d_in[4];
    const float* bhh  = (const float*)d_in[5];
    const float* fcw  = (const float*)d_in[6];
    const float* fcb  = (const float*)d_in[7];
    float* out = (float*)d_out;

    rnn_wavefront_kernel<<<NCTA, NTH>>>(x, Wih0, Wih, Whh, bih, bhh, fcw, fcb, out);
}

// round 6
// speedup vs baseline: 2.1427x; 2.1427x over previous
#include <cuda_runtime.h>

// Fused 6-layer ReLU RNN + FC + log_softmax, diagonal-wavefront persistent kernel.
// R6: layer-specialized lanes with ALL weights in registers (pre-duplicated f32x2).
//     CTA = 512 threads: 480 layer lanes (6 layers x 20 neurons x 4 pair-groups,
//     2 pairs each) + 1 fc/softmax warp. Grid = 128 CTAs (one per SM, single wave).
//     Steady-state SMEM traffic is h-state only (broadcast-friendly).

#define TT 1024
#define BB 2048
#define HH 20
#define LL 6
#define PP 8          // batch-pairs per CTA (pair = 2 batch elems packed f32x2)
#define PSTR 22       // padded h-row stride in 8B units (16B-aligned rows)
#define NTH 512
#define NCTA 128

typedef unsigned long long u64;

__device__ __forceinline__ u64 f2fma(u64 a, u64 b, u64 c) {
    u64 r; asm("fma.rn.f32x2 %0, %1, %2, %3;" : "=l"(r) : "l"(a), "l"(b), "l"(c)); return r;
}
__device__ __forceinline__ u64 f2add(u64 a, u64 b) {
    u64 r; asm("add.rn.f32x2 %0, %1, %2;" : "=l"(r) : "l"(a), "l"(b)); return r;
}
__device__ __forceinline__ u64 dup2(float x) {
    u64 r; asm("mov.b64 %0, {%1, %1};" : "=l"(r) : "f"(x)); return r;
}
__device__ __forceinline__ u64 pk2(float lo, float hi) {
    u64 r; asm("mov.b64 %0, {%1, %2};" : "=l"(r) : "f"(lo), "f"(hi)); return r;
}
__device__ __forceinline__ void unpk(u64 a, float& lo, float& hi) {
    asm("mov.b64 {%0, %1}, %2;" : "=f"(lo), "=f"(hi) : "l"(a));
}

// 20-element f32x2 dot product: weights from register array, h from SMEM.
__device__ __forceinline__ u64 dot20(const u64 (&w)[HH], const u64* hbase, u64 acc) {
    const ulonglong2* h = (const ulonglong2*)hbase;
    u64 a0 = acc, a1 = 0ull, a2 = 0ull, a3 = 0ull;
#pragma unroll
    for (int q = 0; q < 5; q++) {
        ulonglong2 h0 = h[q], h1 = h[q + 5];
        a0 = f2fma(w[2 * q],      h0.x, a0);
        a1 = f2fma(w[2 * q + 1],  h0.y, a1);
        a2 = f2fma(w[2 * q + 10], h1.x, a2);
        a3 = f2fma(w[2 * q + 11], h1.y, a3);
    }
    return f2add(f2add(a0, a1), f2add(a2, a3));
}

__global__ __launch_bounds__(NTH, 1) void rnn_wavefront_kernel(
    const float* __restrict__ x,     // [T, B, 2]
    const float* __restrict__ Wih0,  // [H, 2]
    const float* __restrict__ Wih,   // [L-1, H, H]
    const float* __restrict__ Whh,   // [L, H, H]
    const float* __restrict__ bih,   // [L, H]
    const float* __restrict__ bhh,   // [L, H]
    const float* __restrict__ fcw,   // [2, H]
    const float* __restrict__ fcb,   // [2]
    float* __restrict__ out)         // [T, B, 2]
{
    __shared__ __align__(16) u64 hb[2][LL][PP * PSTR];   // double-buffered h state (f32x2/neuron)
    __shared__ __align__(16) u64 logitb[2][PP][2];       // double-buffered logits

    const int tid = threadIdx.x;

    for (int i = tid; i < 2 * LL * PP * PSTR; i += NTH) ((u64*)hb)[i] = 0ull;
    for (int i = tid; i < 2 * PP * 2; i += NTH)         ((u64*)logitb)[i] = 0ull;

    // ---- role decomposition ----
    const bool is_layer = tid < 480;
    const int l  = tid / 80;              // layer (valid for layer lanes)
    const int u  = tid % 80;
    const int j  = u % 20;                // neuron
    const int ph = u / 20;                // 0..3
    const int p0 = ph, p1 = ph + 4;       // two pairs per lane

    const int fl   = tid - 480;           // 0..31 for the fc/softmax warp
    const int fc_p = (fl & 15) >> 1;      // fc lanes 0..15
    const int fc_c = fl & 1;
    const int sm_p = (fl - 16) >> 1;      // softmax lanes 16..31
    const int sm_w = fl & 1;

    // ---- weights into registers (fc lanes overlay their weights on wh[]) ----
    u64 wh[HH];
    u64 wi[HH];
    u64 bj = 0ull;
#pragma unroll
    for (int k = 0; k < HH; k++) { wh[k] = 0ull; wi[k] = 0ull; }

    if (is_layer) {
#pragma unroll
        for (int k = 0; k < HH; k++) wh[k] = dup2(Whh[(l * HH + j) * HH + k]);
        if (l > 0) {
#pragma unroll
            for (int k = 0; k < HH; k++) wi[k] = dup2(Wih[((l - 1) * HH + j) * HH + k]);
        } else {
            wi[0] = dup2(Wih0[j * 2 + 0]);
            wi[1] = dup2(Wih0[j * 2 + 1]);
        }
        bj = dup2(bih[l * HH + j] + bhh[l * HH + j]);
    } else if (fl < 16) {
#pragma unroll
        for (int k = 0; k < HH; k++) wh[k] = dup2(fcw[fc_c * HH + k]);
        bj = dup2(fcb[fc_c]);
    }

    // ---- layer-0 input staging ----
    const float2* __restrict__ x2 = (const float2*)x;   // x2[t*BB + b]
    float2 xa0, xb0, xa1, xb1;
    int b00 = 0, b01 = 0, b10 = 0, b11 = 0;
    if (is_layer && l == 0) {
        b00 = blockIdx.x * PP + p0; b01 = b00 + (BB / 2);
        b10 = blockIdx.x * PP + p1; b11 = b10 + (BB / 2);
        xa0 = x2[b00]; xb0 = x2[b01];
        xa1 = x2[b10]; xb1 = x2[b11];
    }

    __syncthreads();

    for (int tau = 0; tau < TT + 7; ++tau) {
        const int A = tau & 1;
        const u64(*rb)[PP * PSTR] = hb[A];       // read buffer (last tick)
        u64(*wb)[PP * PSTR] = hb[A ^ 1];         // write buffer (this tick)

        if (is_layer) {
            const int t = tau - l;
            if ((unsigned)t < TT) {
                // pair p0
                {
                    u64 s = dot20(wh, &rb[l][p0 * PSTR], bj);
                    if (l > 0) {
                        s = f2add(s, dot20(wi, &rb[l - 1][p0 * PSTR], 0ull));
                    } else {
                        s = f2add(s, f2add(f2fma(wi[0], pk2(xa0.x, xb0.x), 0ull),
                                           f2fma(wi[1], pk2(xa0.y, xb0.y), 0ull)));
                    }
                    float lo, hi; unpk(s, lo, hi);
                    lo = fmaxf(lo, 0.0f); hi = fmaxf(hi, 0.0f);
                    *(float2*)&wb[l][p0 * PSTR + j] = make_float2(lo, hi);
                }
                // pair p1
                {
                    u64 s = dot20(wh, &rb[l][p1 * PSTR], bj);
                    if (l > 0) {
                        s = f2add(s, dot20(wi, &rb[l - 1][p1 * PSTR], 0ull));
                    } else {
                        s = f2add(s, f2add(f2fma(wi[0], pk2(xa1.x, xb1.x), 0ull),
                                           f2fma(wi[1], pk2(xa1.y, xb1.y), 0ull)));
                    }
                    float lo, hi; unpk(s, lo, hi);
                    lo = fmaxf(lo, 0.0f); hi = fmaxf(hi, 0.0f);
                    *(float2*)&wb[l][p1 * PSTR + j] = make_float2(lo, hi);
                }
            }
            // prefetch next x for layer 0
            if (l == 0 && tau + 1 < TT) {
                const int tn = tau + 1;
                xa0 = x2[tn * BB + b00]; xb0 = x2[tn * BB + b01];
                xa1 = x2[tn * BB + b10]; xb1 = x2[tn * BB + b11];
            }
        } else if (fl < 16) {
            // ---- fc: logits(t = tau - 6) ----
            if ((unsigned)(tau - 6) < TT) {
                logitb[A ^ 1][fc_p][fc_c] = dot20(wh, &rb[5][fc_p * PSTR], bj);
            }
        } else {
            // ---- log_softmax + store, t = tau - 7 ----
            if ((unsigned)(tau - 7) < TT) {
                const int t = tau - 7;
                ulonglong2 lg = *(const ulonglong2*)&logitb[A][sm_p][0];
                float c0a, c0b, c1a, c1b;
                unpk(lg.x, c0a, c0b);   // class-0 logits for (b0, b1)
                unpk(lg.y, c1a, c1b);   // class-1 logits
                float u0 = sm_w ? c0b : c0a;
                float u1 = sm_w ? c1b : c1a;
                float m = fmaxf(u0, u1);
                float lse = m + __logf(1.0f + __expf(fminf(u0, u1) - m));
                const int pg = blockIdx.x * PP + sm_p;
                const int b = sm_w ? pg + (BB / 2) : pg;
                *(float2*)&out[(size_t)(t * BB + b) * 2] = make_float2(u0 - lse, u1 - lse);
            }
        }

        __syncthreads();
    }
}

extern "C" void kernel_launch(void* const* d_in, const int* in_sizes, int n_in,
                              void* d_out, int out_size) {
    const float* x    = (const float*)d_in[0];
    const float* Wih0 = (const float*)d_in[1];
    const float* Wih  = (const float*)d_in[2];
    const float* Whh  = (const float*)d_in[3];
    const float* bih  = (const float*)d_in[4];
    const float* bhh  = (const float*)d_in[5];
    const float* fcw  = (const float*)d_in[6];
    const float* fcb  = (const float*)d_in[7];
    float* out = (float*)d_out;

    rnn_wavefront_kernel<<<NCTA, NTH>>>(x, Wih0, Wih, Whh, bih, bhh, fcw, fcb, out);
}